// round 1
// baseline (speedup 1.0000x reference)
#include <cuda_runtime.h>
#include <math.h>

#define EMBD   1024
#define HEADS  16
#define HD     64
#define BATCH  4
#define SEQ    2048
#define MROWS  (BATCH*SEQ)   // 8192

// ---------------- scratch (allocation-free: __device__ globals) ----------------
__device__ __align__(128) float g_q[BATCH*HEADS*SEQ*HD];   // [B,H,S,Dh]  32 MB
__device__ __align__(128) float g_k[BATCH*SEQ*HD];         // [B,S,Dh]     2 MB
__device__ __align__(128) float g_v[BATCH*SEQ*HD];         // [B,S,Dh]     2 MB
__device__ __align__(128) float g_ao[MROWS*EMBD];          // [B,S,H*Dh]  32 MB

// ---------------- SGEMM 128x128x8, 256 thr, 8x8 micro-tile ----------------
// C = A[M,K] @ B[K,N] + bias.  REMAP=1: scatter output to [B,H,S,Dh] (for Q).
template<int REMAP>
__global__ __launch_bounds__(256, 2)
void sgemm128x128(const float* __restrict__ A, const float* __restrict__ B,
                  const float* __restrict__ bias, float* __restrict__ C,
                  int M, int N, int K)
{
    __shared__ float As[8][128];
    __shared__ float Bs[8][128];
    const int tid = threadIdx.x;
    const int bm = blockIdx.y * 128;
    const int bn = blockIdx.x * 128;

    const int a_row = tid >> 1;            // 0..127
    const int a_col = (tid & 1) * 4;       // 0 or 4
    const int b_row = tid >> 5;            // 0..7
    const int b_col = (tid & 31) * 4;      // 0..124
    const int ty = (tid >> 4) * 8;         // row base of micro-tile
    const int tx = (tid & 15) * 8;         // col base of micro-tile

    float acc[8][8];
#pragma unroll
    for (int i = 0; i < 8; i++)
#pragma unroll
        for (int j = 0; j < 8; j++) acc[i][j] = 0.f;

    const float* Ap = A + (long)(bm + a_row) * K + a_col;
    const float* Bp = B + (long)b_row * N + bn + b_col;

    for (int kt = 0; kt < K; kt += 8) {
        float4 a4 = *(const float4*)(Ap + kt);
        As[a_col + 0][a_row] = a4.x;
        As[a_col + 1][a_row] = a4.y;
        As[a_col + 2][a_row] = a4.z;
        As[a_col + 3][a_row] = a4.w;
        float4 b4 = *(const float4*)(Bp + (long)kt * N);
        *(float4*)&Bs[b_row][b_col] = b4;
        __syncthreads();
#pragma unroll
        for (int k = 0; k < 8; k++) {
            float4 a0 = *(const float4*)&As[k][ty];
            float4 a1 = *(const float4*)&As[k][ty + 4];
            float4 b0 = *(const float4*)&Bs[k][tx];
            float4 b1 = *(const float4*)&Bs[k][tx + 4];
            float ar[8] = {a0.x,a0.y,a0.z,a0.w,a1.x,a1.y,a1.z,a1.w};
            float br[8] = {b0.x,b0.y,b0.z,b0.w,b1.x,b1.y,b1.z,b1.w};
#pragma unroll
            for (int i = 0; i < 8; i++)
#pragma unroll
                for (int j = 0; j < 8; j++)
                    acc[i][j] = fmaf(ar[i], br[j], acc[i][j]);
        }
        __syncthreads();
    }

#pragma unroll
    for (int i = 0; i < 8; i++) {
        const int m = bm + ty + i;
#pragma unroll
        for (int j = 0; j < 8; j++) {
            const int n = bn + tx + j;
            const float v = acc[i][j] + bias[n];
            if (REMAP) {
                const int b_ = m >> 11;          // / SEQ
                const int s  = m & (SEQ - 1);
                const int h  = n >> 6;           // / HD
                const int d  = n & (HD - 1);
                C[(((long)(b_ * HEADS + h) * SEQ) + s) * HD + d] = v;
            } else {
                C[(long)m * N + n] = v;
            }
        }
    }
}

// ---------------- thin GEMM, N=64 (K/V projections) ----------------
__global__ __launch_bounds__(256)
void sgemm_n64(const float* __restrict__ A, const float* __restrict__ B,
               const float* __restrict__ bias, float* __restrict__ C,
               int M, int K)
{
    __shared__ float As[16][64];
    __shared__ float Bs[16][64];
    const int tid = threadIdx.x;
    const int bm = blockIdx.x * 64;

    const int a_row = tid >> 2;           // 0..63
    const int a_col = (tid & 3) * 4;      // 0..12
    const int b_row = tid >> 4;           // 0..15
    const int b_col = (tid & 15) * 4;     // 0..60
    const int ty = (tid >> 4) * 4;
    const int tx = (tid & 15) * 4;

    float acc[4][4];
#pragma unroll
    for (int i = 0; i < 4; i++)
#pragma unroll
        for (int j = 0; j < 4; j++) acc[i][j] = 0.f;

    const float* Ap = A + (long)(bm + a_row) * K + a_col;
    const float* Bp = B + (long)b_row * 64 + b_col;

    for (int kt = 0; kt < K; kt += 16) {
        float4 a4 = *(const float4*)(Ap + kt);
        As[a_col + 0][a_row] = a4.x;
        As[a_col + 1][a_row] = a4.y;
        As[a_col + 2][a_row] = a4.z;
        As[a_col + 3][a_row] = a4.w;
        float4 b4 = *(const float4*)(Bp + (long)kt * 64);
        *(float4*)&Bs[b_row][b_col] = b4;
        __syncthreads();
#pragma unroll
        for (int k = 0; k < 16; k++) {
            float ar[4], br[4];
#pragma unroll
            for (int i = 0; i < 4; i++) ar[i] = As[k][ty + i];
#pragma unroll
            for (int j = 0; j < 4; j++) br[j] = Bs[k][tx + j];
#pragma unroll
            for (int i = 0; i < 4; i++)
#pragma unroll
                for (int j = 0; j < 4; j++)
                    acc[i][j] = fmaf(ar[i], br[j], acc[i][j]);
        }
        __syncthreads();
    }
#pragma unroll
    for (int i = 0; i < 4; i++)
#pragma unroll
        for (int j = 0; j < 4; j++)
            C[(long)(bm + ty + i) * 64 + tx + j] = acc[i][j] + bias[tx + j];
}

// ---------------- flash attention, fp32 ----------------
// grid: (SEQ/64, B*H), 256 threads. Q:[B,H,S,Dh], K/V:[B,S,Dh], O:[B,S,H*Dh]
#define SMP 65                       // padded row stride
#define ATTN_SMEM (4 * 64 * SMP * (int)sizeof(float))

__global__ __launch_bounds__(256)
void attn_kernel(const float* __restrict__ Q, const float* __restrict__ K,
                 const float* __restrict__ V, float* __restrict__ O)
{
    extern __shared__ float sm[];
    float* Qs = sm;
    float* Ks = sm + 64 * SMP;
    float* Vs = sm + 2 * 64 * SMP;
    float* Ss = sm + 3 * 64 * SMP;

    const int tid = threadIdx.x;
    const int bh = blockIdx.y;           // b*HEADS + h
    const int b  = bh >> 4;
    const int h  = bh & 15;
    const int qt = blockIdx.x;

    const float* Qb = Q + ((long)bh * SEQ + qt * 64) * HD;
    const float* Kb = K + (long)b * SEQ * HD;
    const float* Vb = V + (long)b * SEQ * HD;

    // load Q tile
    {
        const int row = tid >> 2;
        const int col = (tid & 3) * 16;
#pragma unroll
        for (int u = 0; u < 4; u++) {
            float4 q4 = *(const float4*)(Qb + row * HD + col + u * 4);
            Qs[row * SMP + col + u*4 + 0] = q4.x;
            Qs[row * SMP + col + u*4 + 1] = q4.y;
            Qs[row * SMP + col + u*4 + 2] = q4.z;
            Qs[row * SMP + col + u*4 + 3] = q4.w;
        }
    }

    const int rq  = (tid >> 4) * 4;     // QK micro-tile rows
    const int cq  = (tid & 15) * 4;     // QK micro-tile cols
    const int r   = tid >> 2;           // softmax/PV row
    const int seg = (tid & 3) * 16;     // col/dim segment

    float m_run = -1e30f, l_run = 0.f;
    float acc[16];
#pragma unroll
    for (int j = 0; j < 16; j++) acc[j] = 0.f;

    const float sc = 0.125f;            // 1/sqrt(64)

    for (int kt = 0; kt < SEQ / 64; kt++) {
        __syncthreads();                // previous PV done before overwriting K/V
        {
            const int row = tid >> 2;
            const int col = (tid & 3) * 16;
            const float* kp = Kb + ((long)kt * 64 + row) * HD + col;
            const float* vp = Vb + ((long)kt * 64 + row) * HD + col;
#pragma unroll
            for (int u = 0; u < 4; u++) {
                float4 k4 = *(const float4*)(kp + u * 4);
                Ks[row*SMP + col + u*4 + 0] = k4.x;
                Ks[row*SMP + col + u*4 + 1] = k4.y;
                Ks[row*SMP + col + u*4 + 2] = k4.z;
                Ks[row*SMP + col + u*4 + 3] = k4.w;
                float4 v4 = *(const float4*)(vp + u * 4);
                Vs[row*SMP + col + u*4 + 0] = v4.x;
                Vs[row*SMP + col + u*4 + 1] = v4.y;
                Vs[row*SMP + col + u*4 + 2] = v4.z;
                Vs[row*SMP + col + u*4 + 3] = v4.w;
            }
        }
        __syncthreads();

        // S = (Q K^T) * sc, 4x4 micro-tile
        float s4[4][4];
#pragma unroll
        for (int i = 0; i < 4; i++)
#pragma unroll
            for (int j = 0; j < 4; j++) s4[i][j] = 0.f;
#pragma unroll 8
        for (int k = 0; k < 64; k++) {
            float qv[4], kv[4];
#pragma unroll
            for (int i = 0; i < 4; i++) qv[i] = Qs[(rq + i) * SMP + k];
#pragma unroll
            for (int j = 0; j < 4; j++) kv[j] = Ks[(cq + j) * SMP + k];
#pragma unroll
            for (int i = 0; i < 4; i++)
#pragma unroll
                for (int j = 0; j < 4; j++)
                    s4[i][j] = fmaf(qv[i], kv[j], s4[i][j]);
        }
#pragma unroll
        for (int i = 0; i < 4; i++)
#pragma unroll
            for (int j = 0; j < 4; j++)
                Ss[(rq + i) * SMP + cq + j] = s4[i][j] * sc;
        __syncthreads();

        // online softmax for row r, cols [seg, seg+16)
        float sloc[16];
        float mloc = -1e30f;
#pragma unroll
        for (int j = 0; j < 16; j++) {
            sloc[j] = Ss[r * SMP + seg + j];
            mloc = fmaxf(mloc, sloc[j]);
        }
        mloc = fmaxf(mloc, __shfl_xor_sync(0xffffffffu, mloc, 1));
        mloc = fmaxf(mloc, __shfl_xor_sync(0xffffffffu, mloc, 2));
        const float m_new = fmaxf(m_run, mloc);
        float ssum = 0.f;
#pragma unroll
        for (int j = 0; j < 16; j++) {
            float p = __expf(sloc[j] - m_new);
            ssum += p;
            Ss[r * SMP + seg + j] = p;
        }
        ssum += __shfl_xor_sync(0xffffffffu, ssum, 1);
        ssum += __shfl_xor_sync(0xffffffffu, ssum, 2);
        const float resc = __expf(m_run - m_new);
        l_run = l_run * resc + ssum;
        m_run = m_new;
#pragma unroll
        for (int j = 0; j < 16; j++) acc[j] *= resc;
        __syncthreads();

        // acc += P @ V
#pragma unroll 4
        for (int c = 0; c < 64; c++) {
            const float p = Ss[r * SMP + c];
#pragma unroll
            for (int j = 0; j < 16; j++)
                acc[j] = fmaf(p, Vs[c * SMP + seg + j], acc[j]);
        }
    }

    const float inv = 1.0f / l_run;
    const int srow = qt * 64 + r;
    float* op = O + (((long)b * SEQ + srow) * HEADS + h) * HD + seg;
#pragma unroll
    for (int j = 0; j < 16; j++) op[j] = acc[j] * inv;
}

// ---------------- launch ----------------
extern "C" void kernel_launch(void* const* d_in, const int* in_sizes, int n_in,
                              void* d_out, int out_size)
{
    const float* x  = (const float*)d_in[0];
    const float* Wq = (const float*)d_in[1];
    const float* bq = (const float*)d_in[2];
    const float* Wk = (const float*)d_in[3];
    const float* bk = (const float*)d_in[4];
    const float* Wv = (const float*)d_in[5];
    const float* bv = (const float*)d_in[6];
    const float* Wo = (const float*)d_in[7];
    const float* bo = (const float*)d_in[8];
    float* out = (float*)d_out;

    float *q, *k, *v, *ao;
    cudaGetSymbolAddress((void**)&q,  g_q);
    cudaGetSymbolAddress((void**)&k,  g_k);
    cudaGetSymbolAddress((void**)&v,  g_v);
    cudaGetSymbolAddress((void**)&ao, g_ao);

    dim3 gP(EMBD / 128, MROWS / 128);   // (8, 64)

    // Q projection -> [B,H,S,Dh]
    sgemm128x128<1><<<gP, 256>>>(x, Wq, bq, q, MROWS, EMBD, EMBD);
    // K / V projections -> [B,S,Dh]
    sgemm_n64<<<MROWS / 64, 256>>>(x, Wk, bk, k, MROWS, EMBD);
    sgemm_n64<<<MROWS / 64, 256>>>(x, Wv, bv, v, MROWS, EMBD);

    // flash attention -> [B,S,H*Dh]
    cudaFuncSetAttribute(attn_kernel, cudaFuncAttributeMaxDynamicSharedMemorySize, ATTN_SMEM);
    attn_kernel<<<dim3(SEQ / 64, BATCH * HEADS), 256, ATTN_SMEM>>>(q, k, v, ao);

    // output projection -> d_out
    sgemm128x128<0><<<gP, 256>>>(ao, Wo, bo, out, MROWS, EMBD, EMBD);
}

// round 2
// speedup vs baseline: 8.6334x; 8.6334x over previous
#include <cuda_runtime.h>
#include <cuda_fp16.h>

#define EMBD   1024
#define HEADS  16
#define HD     64
#define BATCH  4
#define SEQ    2048
#define MROWS  (BATCH*SEQ)   // 8192

// ---------------- scratch (allocation-free: __device__ globals) ----------------
__device__ __align__(128) __half g_xh [MROWS*EMBD];        // x in fp16          16 MB
__device__ __align__(128) __half g_wqt[EMBD*EMBD];         // Wq^T [N][K]         2 MB
__device__ __align__(128) __half g_wkt[HD*EMBD];           // Wk^T [64][1024]
__device__ __align__(128) __half g_wvt[HD*EMBD];           // Wv^T
__device__ __align__(128) __half g_wot[EMBD*EMBD];         // Wo^T                2 MB
__device__ __align__(128) __half g_q  [BATCH*HEADS*SEQ*HD];// Q [B,H,S,Dh]       16 MB
__device__ __align__(128) __half g_k  [BATCH*SEQ*HD];      // K [B,S,Dh]          1 MB
__device__ __align__(128) __half g_vt [BATCH*HD*SEQ];      // V^T [B,Dh,S]        1 MB
__device__ __align__(128) __half g_ao [MROWS*EMBD];        // attn out fp16      16 MB

// ---------------- mma.sync m16n8k16 fp16 -> fp32 ----------------
__device__ __forceinline__ void mma16816(float c[4], const unsigned a[4], const unsigned b[2]) {
    asm volatile(
        "mma.sync.aligned.m16n8k16.row.col.f32.f16.f16.f32 "
        "{%0,%1,%2,%3}, {%4,%5,%6,%7}, {%8,%9}, {%0,%1,%2,%3};\n"
        : "+f"(c[0]), "+f"(c[1]), "+f"(c[2]), "+f"(c[3])
        : "r"(a[0]), "r"(a[1]), "r"(a[2]), "r"(a[3]), "r"(b[0]), "r"(b[1]));
}

// ---------------- fp32 -> fp16 convert ----------------
__global__ void f2h_kernel(const float* __restrict__ in, __half* __restrict__ out, int n4) {
    int i = blockIdx.x * blockDim.x + threadIdx.x;
    if (i < n4) {
        float4 v = ((const float4*)in)[i];
        __half2* o = (__half2*)out + (size_t)i * 2;
        o[0] = __floats2half2_rn(v.x, v.y);
        o[1] = __floats2half2_rn(v.z, v.w);
    }
}

// ---------------- fp32 [R][C] -> fp16 [C][R] transpose-convert ----------------
__global__ void tconv_kernel(const float* __restrict__ in, __half* __restrict__ out, int R, int C) {
    __shared__ float t[32][33];
    const int c0 = blockIdx.x * 32, r0 = blockIdx.y * 32;
    const int tx = threadIdx.x, ty = threadIdx.y;
#pragma unroll
    for (int j = 0; j < 32; j += 8)
        t[ty + j][tx] = in[(size_t)(r0 + ty + j) * C + c0 + tx];
    __syncthreads();
#pragma unroll
    for (int j = 0; j < 32; j += 8)
        out[(size_t)(c0 + ty + j) * R + r0 + tx] = __float2half(t[tx][ty + j]);
}

// ---------------- HGEMM: C = A[M,K] @ Bt[N,K]^T + bias ----------------
// EPI: 0 = fp32 row-major [m][n]; 1 = fp16 row-major stride 64 (K proj);
//      2 = fp16 remap to [B,H,S,Dh] (Q proj); 3 = fp16 transposed [B,Dh,S] (V proj)
template<int BN, int EPI>
__global__ __launch_bounds__(256)
void hgemm_kernel(const __half* __restrict__ A, const __half* __restrict__ Bt,
                  const float* __restrict__ bias, void* __restrict__ Cout,
                  int K, int N)
{
    constexpr int BM = 128, BK = 32;
    constexpr int WARPS_N = BN / 32;          // 4 or 2
    constexpr int WARPS_M = 8 / WARPS_N;      // 2 or 4
    constexpr int WM = BM / WARPS_M;          // 64 or 32
    constexpr int MF = WM / 16;               // 4 or 2
    constexpr int NF = 4;

    __shared__ __half As[BM][40];
    __shared__ __half Bs[BN][40];

    const int tid  = threadIdx.x;
    const int bm   = blockIdx.y * BM, bn = blockIdx.x * BN;
    const int warp = tid >> 5, lane = tid & 31;
    const int wm   = warp / WARPS_N, wn = warp % WARPS_N;
    const int g    = lane >> 2, t2 = (lane & 3) * 2;
    const int lr   = tid >> 2, lc = (tid & 3) * 8;

    float acc[MF][NF][4];
#pragma unroll
    for (int i = 0; i < MF; i++)
#pragma unroll
        for (int j = 0; j < NF; j++)
#pragma unroll
            for (int q = 0; q < 4; q++) acc[i][j][q] = 0.f;

    const int nk = K / BK;
    uint4 ra0, ra1, rb0, rb1;
    {
        ra0 = *(const uint4*)&A[(size_t)(bm + lr) * K + lc];
        ra1 = *(const uint4*)&A[(size_t)(bm + lr + 64) * K + lc];
        rb0 = *(const uint4*)&Bt[(size_t)(bn + lr) * K + lc];
        if (BN == 128) rb1 = *(const uint4*)&Bt[(size_t)(bn + lr + 64) * K + lc];
    }

    for (int kt = 0; kt < nk; kt++) {
        *(uint4*)&As[lr][lc]      = ra0;
        *(uint4*)&As[lr + 64][lc] = ra1;
        *(uint4*)&Bs[lr][lc]      = rb0;
        if (BN == 128) *(uint4*)&Bs[lr + 64][lc] = rb1;
        __syncthreads();

        if (kt + 1 < nk) {
            const int ko = (kt + 1) * BK + lc;
            ra0 = *(const uint4*)&A[(size_t)(bm + lr) * K + ko];
            ra1 = *(const uint4*)&A[(size_t)(bm + lr + 64) * K + ko];
            rb0 = *(const uint4*)&Bt[(size_t)(bn + lr) * K + ko];
            if (BN == 128) rb1 = *(const uint4*)&Bt[(size_t)(bn + lr + 64) * K + ko];
        }

#pragma unroll
        for (int ks = 0; ks < BK; ks += 16) {
            unsigned af[MF][4], bf[NF][2];
#pragma unroll
            for (int mf = 0; mf < MF; mf++) {
                const int row = wm * WM + mf * 16 + g;
                af[mf][0] = *(const unsigned*)&As[row][ks + t2];
                af[mf][1] = *(const unsigned*)&As[row + 8][ks + t2];
                af[mf][2] = *(const unsigned*)&As[row][ks + t2 + 8];
                af[mf][3] = *(const unsigned*)&As[row + 8][ks + t2 + 8];
            }
#pragma unroll
            for (int nf = 0; nf < NF; nf++) {
                const int col = wn * 32 + nf * 8 + g;
                bf[nf][0] = *(const unsigned*)&Bs[col][ks + t2];
                bf[nf][1] = *(const unsigned*)&Bs[col][ks + t2 + 8];
            }
#pragma unroll
            for (int mf = 0; mf < MF; mf++)
#pragma unroll
                for (int nf = 0; nf < NF; nf++)
                    mma16816(acc[mf][nf], af[mf], bf[nf]);
        }
        __syncthreads();
    }

    // epilogue
#pragma unroll
    for (int mf = 0; mf < MF; mf++) {
#pragma unroll
        for (int nf = 0; nf < NF; nf++) {
            const int m = bm + wm * WM + mf * 16 + g;
            const int n = bn + wn * 32 + nf * 8 + t2;
            const float b0 = bias[n], b1 = bias[n + 1];
            const float v00 = acc[mf][nf][0] + b0, v01 = acc[mf][nf][1] + b1;
            const float v10 = acc[mf][nf][2] + b0, v11 = acc[mf][nf][3] + b1;
            if (EPI == 0) {
                float* C = (float*)Cout;
                *(float2*)&C[(size_t)m * N + n]       = make_float2(v00, v01);
                *(float2*)&C[(size_t)(m + 8) * N + n] = make_float2(v10, v11);
            } else if (EPI == 1) {
                __half* C = (__half*)Cout;
                *(__half2*)&C[(size_t)m * 64 + n]       = __floats2half2_rn(v00, v01);
                *(__half2*)&C[(size_t)(m + 8) * 64 + n] = __floats2half2_rn(v10, v11);
            } else if (EPI == 2) {
                __half* C = (__half*)Cout;
                const int h = n >> 6, d = n & 63;
                const int b_ = m >> 11, s = m & (SEQ - 1);
                *(__half2*)&C[(((size_t)(b_ * HEADS + h) * SEQ) + s) * HD + d] =
                    __floats2half2_rn(v00, v01);
                *(__half2*)&C[(((size_t)(b_ * HEADS + h) * SEQ) + s + 8) * HD + d] =
                    __floats2half2_rn(v10, v11);
            } else {
                __half* C = (__half*)Cout;
                const int b_ = m >> 11, s = m & (SEQ - 1);
                C[((size_t)(b_ * HD) + n)     * SEQ + s]     = __float2half(v00);
                C[((size_t)(b_ * HD) + n + 1) * SEQ + s]     = __float2half(v01);
                C[((size_t)(b_ * HD) + n)     * SEQ + s + 8] = __float2half(v10);
                C[((size_t)(b_ * HD) + n + 1) * SEQ + s + 8] = __float2half(v11);
            }
        }
    }
}

// ---------------- flash attention, fp16 tensor cores ----------------
// grid (SEQ/64, B*H), 256 thr. Q[B,H,S,Dh] fp16, K[B,S,Dh] fp16, Vt[B,Dh,S] fp16
// out: ao [B,S,H*Dh] fp16
#define ATTN_SMEM (4*64*72*2 + 64*68*4 + 3*64*4)   // 55040 B

__global__ __launch_bounds__(256)
void attn_kernel(const __half* __restrict__ Q, const __half* __restrict__ Kg,
                 const __half* __restrict__ Vt, __half* __restrict__ O)
{
    extern __shared__ char smraw[];
    __half* Qs = (__half*)smraw;            // [64][72]
    __half* Ks = Qs + 64 * 72;
    __half* Vs = Ks + 64 * 72;              // [d][t]
    __half* Ps = Vs + 64 * 72;
    float*  Ss = (float*)(Ps + 64 * 72);    // [64][68]
    float*  mrow = Ss + 64 * 68;
    float*  lrow = mrow + 64;
    float*  rrow = lrow + 64;

    const int tid  = threadIdx.x;
    const int bh   = blockIdx.y, b = bh >> 4, h = bh & 15, qt = blockIdx.x;
    const int warp = tid >> 5, lane = tid & 31;
    const int wm   = warp >> 2, wn = warp & 3;         // 2 x 4 warps
    const int g    = lane >> 2, t2 = (lane & 3) * 2;
    const int lr   = tid >> 2, lc = (tid & 3) * 16;

    // load Q tile (persistent)
    {
        const __half* Qb = Q + ((size_t)bh * SEQ + qt * 64) * HD;
        *(uint4*)&Qs[lr * 72 + lc]     = *(const uint4*)&Qb[lr * HD + lc];
        *(uint4*)&Qs[lr * 72 + lc + 8] = *(const uint4*)&Qb[lr * HD + lc + 8];
    }
    if (tid < 64) { mrow[tid] = -1e30f; lrow[tid] = 0.f; }

    float oacc[2][2][4];
#pragma unroll
    for (int i = 0; i < 2; i++)
#pragma unroll
        for (int j = 0; j < 2; j++)
#pragma unroll
            for (int q = 0; q < 4; q++) oacc[i][j][q] = 0.f;

    const float scl = 0.125f;   // 1/sqrt(64)

    for (int kt = 0; kt < SEQ / 64; kt++) {
        __syncthreads();   // prior PV reads of Ks/Vs done
        {
            const __half* Kb = Kg + ((size_t)b * SEQ + kt * 64) * HD;
            *(uint4*)&Ks[lr * 72 + lc]     = *(const uint4*)&Kb[lr * HD + lc];
            *(uint4*)&Ks[lr * 72 + lc + 8] = *(const uint4*)&Kb[lr * HD + lc + 8];
            const __half* Vb = Vt + ((size_t)b * HD + lr) * SEQ + kt * 64;
            *(uint4*)&Vs[lr * 72 + lc]     = *(const uint4*)&Vb[lc];
            *(uint4*)&Vs[lr * 72 + lc + 8] = *(const uint4*)&Vb[lc + 8];
        }
        __syncthreads();

        // S = Q @ K^T
        float sacc[2][2][4];
#pragma unroll
        for (int i = 0; i < 2; i++)
#pragma unroll
            for (int j = 0; j < 2; j++)
#pragma unroll
                for (int q = 0; q < 4; q++) sacc[i][j][q] = 0.f;
#pragma unroll
        for (int ks = 0; ks < 64; ks += 16) {
            unsigned af[2][4], bf[2][2];
#pragma unroll
            for (int mf = 0; mf < 2; mf++) {
                const int row = wm * 32 + mf * 16 + g;
                af[mf][0] = *(const unsigned*)&Qs[row * 72 + ks + t2];
                af[mf][1] = *(const unsigned*)&Qs[(row + 8) * 72 + ks + t2];
                af[mf][2] = *(const unsigned*)&Qs[row * 72 + ks + t2 + 8];
                af[mf][3] = *(const unsigned*)&Qs[(row + 8) * 72 + ks + t2 + 8];
            }
#pragma unroll
            for (int nf = 0; nf < 2; nf++) {
                const int col = wn * 16 + nf * 8 + g;
                bf[nf][0] = *(const unsigned*)&Ks[col * 72 + ks + t2];
                bf[nf][1] = *(const unsigned*)&Ks[col * 72 + ks + t2 + 8];
            }
#pragma unroll
            for (int mf = 0; mf < 2; mf++)
#pragma unroll
                for (int nf = 0; nf < 2; nf++)
                    mma16816(sacc[mf][nf], af[mf], bf[nf]);
        }
#pragma unroll
        for (int mf = 0; mf < 2; mf++)
#pragma unroll
            for (int nf = 0; nf < 2; nf++) {
                const int m0 = wm * 32 + mf * 16, n0 = wn * 16 + nf * 8;
                Ss[(m0 + g) * 68 + n0 + t2]         = sacc[mf][nf][0] * scl;
                Ss[(m0 + g) * 68 + n0 + t2 + 1]     = sacc[mf][nf][1] * scl;
                Ss[(m0 + 8 + g) * 68 + n0 + t2]     = sacc[mf][nf][2] * scl;
                Ss[(m0 + 8 + g) * 68 + n0 + t2 + 1] = sacc[mf][nf][3] * scl;
            }
        __syncthreads();

        // online softmax (row lr, 16-col segment lc)
        {
            const int r = lr, seg = lc;
            float sl[16];
            float mloc = -1e30f;
#pragma unroll
            for (int j = 0; j < 16; j++) { sl[j] = Ss[r * 68 + seg + j]; mloc = fmaxf(mloc, sl[j]); }
            mloc = fmaxf(mloc, __shfl_xor_sync(0xffffffffu, mloc, 1));
            mloc = fmaxf(mloc, __shfl_xor_sync(0xffffffffu, mloc, 2));
            const float mo = mrow[r];
            const float mn = fmaxf(mo, mloc);
            float ssum = 0.f;
#pragma unroll
            for (int j = 0; j < 16; j++) {
                float p = __expf(sl[j] - mn);
                ssum += p;
                Ps[r * 72 + seg + j] = __float2half(p);
            }
            ssum += __shfl_xor_sync(0xffffffffu, ssum, 1);
            ssum += __shfl_xor_sync(0xffffffffu, ssum, 2);
            if ((tid & 3) == 0) {
                const float rs = __expf(mo - mn);
                lrow[r] = lrow[r] * rs + ssum;
                mrow[r] = mn;
                rrow[r] = rs;
            }
        }
        __syncthreads();

        // rescale + O += P @ V
#pragma unroll
        for (int mf = 0; mf < 2; mf++) {
            const float r0 = rrow[wm * 32 + mf * 16 + g];
            const float r1 = rrow[wm * 32 + mf * 16 + 8 + g];
#pragma unroll
            for (int nf = 0; nf < 2; nf++) {
                oacc[mf][nf][0] *= r0; oacc[mf][nf][1] *= r0;
                oacc[mf][nf][2] *= r1; oacc[mf][nf][3] *= r1;
            }
        }
#pragma unroll
        for (int ks = 0; ks < 64; ks += 16) {
            unsigned af[2][4], bf[2][2];
#pragma unroll
            for (int mf = 0; mf < 2; mf++) {
                const int row = wm * 32 + mf * 16 + g;
                af[mf][0] = *(const unsigned*)&Ps[row * 72 + ks + t2];
                af[mf][1] = *(const unsigned*)&Ps[(row + 8) * 72 + ks + t2];
                af[mf][2] = *(const unsigned*)&Ps[row * 72 + ks + t2 + 8];
                af[mf][3] = *(const unsigned*)&Ps[(row + 8) * 72 + ks + t2 + 8];
            }
#pragma unroll
            for (int nf = 0; nf < 2; nf++) {
                const int col = wn * 16 + nf * 8 + g;
                bf[nf][0] = *(const unsigned*)&Vs[col * 72 + ks + t2];
                bf[nf][1] = *(const unsigned*)&Vs[col * 72 + ks + t2 + 8];
            }
#pragma unroll
            for (int mf = 0; mf < 2; mf++)
#pragma unroll
                for (int nf = 0; nf < 2; nf++)
                    mma16816(oacc[mf][nf], af[mf], bf[nf]);
        }
    }

    // epilogue: divide by l, write [B,S,H*Dh] fp16
#pragma unroll
    for (int mf = 0; mf < 2; mf++) {
        const int m0 = wm * 32 + mf * 16 + g;
        const float i0 = 1.f / lrow[m0];
        const float i1 = 1.f / lrow[m0 + 8];
        const int s0 = qt * 64 + m0;
#pragma unroll
        for (int nf = 0; nf < 2; nf++) {
            const int n0 = wn * 16 + nf * 8 + t2;
            *(__half2*)&O[((size_t)(b * SEQ) + s0) * EMBD + h * HD + n0] =
                __floats2half2_rn(oacc[mf][nf][0] * i0, oacc[mf][nf][1] * i0);
            *(__half2*)&O[((size_t)(b * SEQ) + s0 + 8) * EMBD + h * HD + n0] =
                __floats2half2_rn(oacc[mf][nf][2] * i1, oacc[mf][nf][3] * i1);
        }
    }
}

// ---------------- launch ----------------
extern "C" void kernel_launch(void* const* d_in, const int* in_sizes, int n_in,
                              void* d_out, int out_size)
{
    const float* x  = (const float*)d_in[0];
    const float* Wq = (const float*)d_in[1];
    const float* bq = (const float*)d_in[2];
    const float* Wk = (const float*)d_in[3];
    const float* bk = (const float*)d_in[4];
    const float* Wv = (const float*)d_in[5];
    const float* bv = (const float*)d_in[6];
    const float* Wo = (const float*)d_in[7];
    const float* bo = (const float*)d_in[8];
    float* out = (float*)d_out;

    __half *xh, *wqt, *wkt, *wvt, *wot, *q, *k, *vt, *ao;
    cudaGetSymbolAddress((void**)&xh,  g_xh);
    cudaGetSymbolAddress((void**)&wqt, g_wqt);
    cudaGetSymbolAddress((void**)&wkt, g_wkt);
    cudaGetSymbolAddress((void**)&wvt, g_wvt);
    cudaGetSymbolAddress((void**)&wot, g_wot);
    cudaGetSymbolAddress((void**)&q,   g_q);
    cudaGetSymbolAddress((void**)&k,   g_k);
    cudaGetSymbolAddress((void**)&vt,  g_vt);
    cudaGetSymbolAddress((void**)&ao,  g_ao);

    // fp16 conversions / weight transposes
    f2h_kernel<<<(MROWS * EMBD / 4 + 255) / 256, 256>>>(x, xh, MROWS * EMBD / 4);
    tconv_kernel<<<dim3(EMBD / 32, EMBD / 32), dim3(32, 8)>>>(Wq, wqt, EMBD, EMBD);
    tconv_kernel<<<dim3(HD   / 32, EMBD / 32), dim3(32, 8)>>>(Wk, wkt, EMBD, HD);
    tconv_kernel<<<dim3(HD   / 32, EMBD / 32), dim3(32, 8)>>>(Wv, wvt, EMBD, HD);
    tconv_kernel<<<dim3(EMBD / 32, EMBD / 32), dim3(32, 8)>>>(Wo, wot, EMBD, EMBD);

    // projections
    hgemm_kernel<128, 2><<<dim3(EMBD / 128, MROWS / 128), 256>>>(xh, wqt, bq, q,  EMBD, EMBD);
    hgemm_kernel<64,  1><<<dim3(1,          MROWS / 128), 256>>>(xh, wkt, bk, k,  EMBD, HD);
    hgemm_kernel<64,  3><<<dim3(1,          MROWS / 128), 256>>>(xh, wvt, bv, vt, EMBD, HD);

    // flash attention
    cudaFuncSetAttribute(attn_kernel, cudaFuncAttributeMaxDynamicSharedMemorySize, ATTN_SMEM);
    attn_kernel<<<dim3(SEQ / 64, BATCH * HEADS), 256, ATTN_SMEM>>>(q, k, vt, ao);

    // output projection -> fp32 d_out
    hgemm_kernel<128, 0><<<dim3(EMBD / 128, MROWS / 128), 256>>>(ao, wot, bo, out, EMBD, EMBD);
}

// round 4
// speedup vs baseline: 12.8716x; 1.4909x over previous
#include <cuda_runtime.h>
#include <cuda_fp16.h>

#define EMBD   1024
#define HEADS  16
#define HD     64
#define BATCH  4
#define SEQ    2048
#define MROWS  (BATCH*SEQ)   // 8192

// ---------------- scratch (allocation-free: __device__ globals) ----------------
__device__ __align__(128) __half g_xh  [MROWS*EMBD];        // x in fp16
__device__ __align__(128) __half g_wqt [EMBD*EMBD];         // Wq^T [N][K]
__device__ __align__(128) __half g_wkvt[2*HD*EMBD];         // [Wk^T ; Wv^T] [128][1024]
__device__ __align__(128) __half g_wot [EMBD*EMBD];         // Wo^T
__device__ __align__(128) float  g_bkv [2*HD];              // [bk ; bv]
__device__ __align__(128) __half g_q   [BATCH*HEADS*SEQ*HD];// Q [B,H,S,Dh]
__device__ __align__(128) __half g_k   [BATCH*SEQ*HD];      // K [B,S,Dh]
__device__ __align__(128) __half g_vt  [BATCH*HD*SEQ];      // V^T [B,Dh,S]
__device__ __align__(128) __half g_ao  [MROWS*EMBD];        // attn out fp16

// ---------------- helpers ----------------
__device__ __forceinline__ unsigned h2_as_u32(__half2 h) {
    return *reinterpret_cast<unsigned*>(&h);
}

// ---------------- mma.sync m16n8k16 fp16 -> fp32 ----------------
__device__ __forceinline__ void mma16816(float c[4], const unsigned a[4], const unsigned b[2]) {
    asm volatile(
        "mma.sync.aligned.m16n8k16.row.col.f32.f16.f16.f32 "
        "{%0,%1,%2,%3}, {%4,%5,%6,%7}, {%8,%9}, {%0,%1,%2,%3};\n"
        : "+f"(c[0]), "+f"(c[1]), "+f"(c[2]), "+f"(c[3])
        : "r"(a[0]), "r"(a[1]), "r"(a[2]), "r"(a[3]), "r"(b[0]), "r"(b[1]));
}

// ---------------- fp32 -> fp16 convert ----------------
__global__ void f2h_kernel(const float* __restrict__ in, __half* __restrict__ out, int n4) {
    int i = blockIdx.x * blockDim.x + threadIdx.x;
    if (i < n4) {
        float4 v = ((const float4*)in)[i];
        __half2* o = (__half2*)out + (size_t)i * 2;
        o[0] = __floats2half2_rn(v.x, v.y);
        o[1] = __floats2half2_rn(v.z, v.w);
    }
}

// ---------------- fp32 [R][C] -> fp16 [C][R] transpose-convert ----------------
__global__ void tconv_kernel(const float* __restrict__ in, __half* __restrict__ out, int R, int C) {
    __shared__ float t[32][33];
    const int c0 = blockIdx.x * 32, r0 = blockIdx.y * 32;
    const int tx = threadIdx.x, ty = threadIdx.y;
#pragma unroll
    for (int j = 0; j < 32; j += 8)
        t[ty + j][tx] = in[(size_t)(r0 + ty + j) * C + c0 + tx];
    __syncthreads();
#pragma unroll
    for (int j = 0; j < 32; j += 8)
        out[(size_t)(c0 + ty + j) * R + r0 + tx] = __float2half(t[tx][ty + j]);
}

__global__ void bcat_kernel(const float* __restrict__ a, const float* __restrict__ b,
                            float* __restrict__ o) {
    int i = threadIdx.x;
    o[i] = (i < HD) ? a[i] : b[i - HD];
}

// ---------------- HGEMM: C = A[M,K] @ Bt[N,K]^T + bias ----------------
// EPI: 0 = fp32 row-major; 2 = fp16 remap to [B,H,S,Dh] (Q proj);
//      4 = fused KV: cols 0-63 -> K [B,S,64], cols 64-127 -> V^T [B,Dh,S]
template<int BN, int EPI>
__global__ __launch_bounds__(256)
void hgemm_kernel(const __half* __restrict__ A, const __half* __restrict__ Bt,
                  const float* __restrict__ bias, void* __restrict__ Cout,
                  int K, int N)
{
    constexpr int BM = 128, BK = 32;
    constexpr int WARPS_N = BN / 32;
    constexpr int WARPS_M = 8 / WARPS_N;
    constexpr int WM = BM / WARPS_M;
    constexpr int MF = WM / 16;
    constexpr int NF = 4;

    __shared__ __half As[BM][40];
    __shared__ __half Bs[BN][40];

    const int tid  = threadIdx.x;
    const int bm   = blockIdx.y * BM, bn = blockIdx.x * BN;
    const int warp = tid >> 5, lane = tid & 31;
    const int wm   = warp / WARPS_N, wn = warp % WARPS_N;
    const int g    = lane >> 2, t2 = (lane & 3) * 2;
    const int lr   = tid >> 2, lc = (tid & 3) * 8;

    float acc[MF][NF][4];
#pragma unroll
    for (int i = 0; i < MF; i++)
#pragma unroll
        for (int j = 0; j < NF; j++)
#pragma unroll
            for (int q = 0; q < 4; q++) acc[i][j][q] = 0.f;

    const int nk = K / BK;
    uint4 ra0, ra1, rb0, rb1;
    ra0 = *(const uint4*)&A[(size_t)(bm + lr) * K + lc];
    ra1 = *(const uint4*)&A[(size_t)(bm + lr + 64) * K + lc];
    rb0 = *(const uint4*)&Bt[(size_t)(bn + lr) * K + lc];
    if (BN == 128) rb1 = *(const uint4*)&Bt[(size_t)(bn + lr + 64) * K + lc];

    for (int kt = 0; kt < nk; kt++) {
        *(uint4*)&As[lr][lc]      = ra0;
        *(uint4*)&As[lr + 64][lc] = ra1;
        *(uint4*)&Bs[lr][lc]      = rb0;
        if (BN == 128) *(uint4*)&Bs[lr + 64][lc] = rb1;
        __syncthreads();

        if (kt + 1 < nk) {
            const int ko = (kt + 1) * BK + lc;
            ra0 = *(const uint4*)&A[(size_t)(bm + lr) * K + ko];
            ra1 = *(const uint4*)&A[(size_t)(bm + lr + 64) * K + ko];
            rb0 = *(const uint4*)&Bt[(size_t)(bn + lr) * K + ko];
            if (BN == 128) rb1 = *(const uint4*)&Bt[(size_t)(bn + lr + 64) * K + ko];
        }

#pragma unroll
        for (int ks = 0; ks < BK; ks += 16) {
            unsigned af[MF][4], bf[NF][2];
#pragma unroll
            for (int mf = 0; mf < MF; mf++) {
                const int row = wm * WM + mf * 16 + g;
                af[mf][0] = *(const unsigned*)&As[row][ks + t2];
                af[mf][1] = *(const unsigned*)&As[row + 8][ks + t2];
                af[mf][2] = *(const unsigned*)&As[row][ks + t2 + 8];
                af[mf][3] = *(const unsigned*)&As[row + 8][ks + t2 + 8];
            }
#pragma unroll
            for (int nf = 0; nf < NF; nf++) {
                const int col = wn * 32 + nf * 8 + g;
                bf[nf][0] = *(const unsigned*)&Bs[col][ks + t2];
                bf[nf][1] = *(const unsigned*)&Bs[col][ks + t2 + 8];
            }
#pragma unroll
            for (int mf = 0; mf < MF; mf++)
#pragma unroll
                for (int nf = 0; nf < NF; nf++)
                    mma16816(acc[mf][nf], af[mf], bf[nf]);
        }
        __syncthreads();
    }

#pragma unroll
    for (int mf = 0; mf < MF; mf++) {
#pragma unroll
        for (int nf = 0; nf < NF; nf++) {
            const int m = bm + wm * WM + mf * 16 + g;
            const int n = bn + wn * 32 + nf * 8 + t2;
            const float b0 = bias[n], b1 = bias[n + 1];
            const float v00 = acc[mf][nf][0] + b0, v01 = acc[mf][nf][1] + b1;
            const float v10 = acc[mf][nf][2] + b0, v11 = acc[mf][nf][3] + b1;
            if (EPI == 0) {
                float* C = (float*)Cout;
                *(float2*)&C[(size_t)m * N + n]       = make_float2(v00, v01);
                *(float2*)&C[(size_t)(m + 8) * N + n] = make_float2(v10, v11);
            } else if (EPI == 2) {
                __half* C = (__half*)Cout;
                const int h = n >> 6, d = n & 63;
                const int b_ = m >> 11, s = m & (SEQ - 1);
                *(__half2*)&C[(((size_t)(b_ * HEADS + h) * SEQ) + s) * HD + d] =
                    __floats2half2_rn(v00, v01);
                *(__half2*)&C[(((size_t)(b_ * HEADS + h) * SEQ) + s + 8) * HD + d] =
                    __floats2half2_rn(v10, v11);
            } else { // EPI == 4, fused KV
                const int b_ = m >> 11, s = m & (SEQ - 1);
                if (n < HD) {
                    __half* C = (__half*)Cout;
                    *(__half2*)&C[((size_t)(b_ * SEQ) + s) * HD + n]     = __floats2half2_rn(v00, v01);
                    *(__half2*)&C[((size_t)(b_ * SEQ) + s + 8) * HD + n] = __floats2half2_rn(v10, v11);
                } else {
                    const int d = n - HD;
                    g_vt[((size_t)(b_ * HD) + d)     * SEQ + s]     = __float2half(v00);
                    g_vt[((size_t)(b_ * HD) + d + 1) * SEQ + s]     = __float2half(v01);
                    g_vt[((size_t)(b_ * HD) + d)     * SEQ + s + 8] = __float2half(v10);
                    g_vt[((size_t)(b_ * HD) + d + 1) * SEQ + s + 8] = __float2half(v11);
                }
            }
        }
    }
}

// ---------------- flash attention, registers-only S/P ----------------
// grid (SEQ/128, B*H), 256 thr (8 warps x 16 rows). Q[B,H,S,Dh], K[B,S,Dh], Vt[B,Dh,S]
__global__ __launch_bounds__(256)
void attn_kernel(const __half* __restrict__ Q, const __half* __restrict__ Kg,
                 const __half* __restrict__ Vt, __half* __restrict__ O)
{
    __shared__ __half Qs[128][72];
    __shared__ __half Ks[64][72];
    __shared__ __half Vs[64][72];   // [d][kv]

    const int tid  = threadIdx.x;
    const int bh   = blockIdx.y, b = bh >> 4, h = bh & 15, qt = blockIdx.x;
    const int warp = tid >> 5, lane = tid & 31;
    const int g    = lane >> 2, t2 = (lane & 3) * 2;

    // load Q tile 128x64 -> smem -> persistent A fragments
    {
        const __half* Qb = Q + ((size_t)bh * SEQ + qt * 128) * HD;
        const int lr = tid >> 1, lc = (tid & 1) * 32;
#pragma unroll
        for (int u = 0; u < 4; u++)
            *(uint4*)&Qs[lr][lc + u * 8] = *(const uint4*)&Qb[lr * HD + lc + u * 8];
    }
    __syncthreads();
    unsigned qf[4][4];
    {
        const int row = warp * 16 + g;
#pragma unroll
        for (int kb = 0; kb < 4; kb++) {
            qf[kb][0] = *(const unsigned*)&Qs[row][kb * 16 + t2];
            qf[kb][1] = *(const unsigned*)&Qs[row + 8][kb * 16 + t2];
            qf[kb][2] = *(const unsigned*)&Qs[row][kb * 16 + t2 + 8];
            qf[kb][3] = *(const unsigned*)&Qs[row + 8][kb * 16 + t2 + 8];
        }
    }

    float oacc[8][4];
#pragma unroll
    for (int nf = 0; nf < 8; nf++)
#pragma unroll
        for (int q = 0; q < 4; q++) oacc[nf][q] = 0.f;
    float m0 = -1e30f, m1 = -1e30f, l0 = 0.f, l1 = 0.f;
    const float scl = 0.125f;

    const __half* Kb = Kg + (size_t)b * SEQ * HD;
    const __half* Vb = Vt + (size_t)b * HD * SEQ;

    // K/V staging: 512 uint4 each, 2 per thread
    const int r0c = tid >> 3,           cu0 = (tid & 7) * 8;
    const int r1c = (tid + 256) >> 3,   cu1 = ((tid + 256) & 7) * 8;

    uint4 kr0, kr1, vr0, vr1;
    kr0 = *(const uint4*)&Kb[(size_t)r0c * HD + cu0];
    kr1 = *(const uint4*)&Kb[(size_t)r1c * HD + cu1];
    vr0 = *(const uint4*)&Vb[(size_t)r0c * SEQ + cu0];
    vr1 = *(const uint4*)&Vb[(size_t)r1c * SEQ + cu1];

    for (int kt = 0; kt < SEQ / 64; kt++) {
        if (kt) __syncthreads();
        *(uint4*)&Ks[r0c][cu0] = kr0;
        *(uint4*)&Ks[r1c][cu1] = kr1;
        *(uint4*)&Vs[r0c][cu0] = vr0;
        *(uint4*)&Vs[r1c][cu1] = vr1;
        __syncthreads();

        if (kt + 1 < SEQ / 64) {
            const int kvo = (kt + 1) * 64;
            kr0 = *(const uint4*)&Kb[((size_t)kvo + r0c) * HD + cu0];
            kr1 = *(const uint4*)&Kb[((size_t)kvo + r1c) * HD + cu1];
            vr0 = *(const uint4*)&Vb[(size_t)r0c * SEQ + kvo + cu0];
            vr1 = *(const uint4*)&Vb[(size_t)r1c * SEQ + kvo + cu1];
        }

        // S = Q @ K^T  (warp: 16 rows x 64 cols, in registers)
        float sacc[8][4];
#pragma unroll
        for (int nf = 0; nf < 8; nf++)
#pragma unroll
            for (int q = 0; q < 4; q++) sacc[nf][q] = 0.f;
#pragma unroll
        for (int kb = 0; kb < 4; kb++) {
#pragma unroll
            for (int nf = 0; nf < 8; nf++) {
                unsigned bf[2];
                bf[0] = *(const unsigned*)&Ks[nf * 8 + g][kb * 16 + t2];
                bf[1] = *(const unsigned*)&Ks[nf * 8 + g][kb * 16 + t2 + 8];
                mma16816(sacc[nf], qf[kb], bf);
            }
        }

        // online softmax in registers
        float mx0 = -1e30f, mx1 = -1e30f;
#pragma unroll
        for (int nf = 0; nf < 8; nf++) {
#pragma unroll
            for (int q = 0; q < 4; q++) sacc[nf][q] *= scl;
            mx0 = fmaxf(mx0, fmaxf(sacc[nf][0], sacc[nf][1]));
            mx1 = fmaxf(mx1, fmaxf(sacc[nf][2], sacc[nf][3]));
        }
        mx0 = fmaxf(mx0, __shfl_xor_sync(0xffffffffu, mx0, 1));
        mx0 = fmaxf(mx0, __shfl_xor_sync(0xffffffffu, mx0, 2));
        mx1 = fmaxf(mx1, __shfl_xor_sync(0xffffffffu, mx1, 1));
        mx1 = fmaxf(mx1, __shfl_xor_sync(0xffffffffu, mx1, 2));
        const float mn0 = fmaxf(m0, mx0), mn1 = fmaxf(m1, mx1);

        unsigned ph[8][2];
        float ps0 = 0.f, ps1 = 0.f;
#pragma unroll
        for (int nf = 0; nf < 8; nf++) {
            const float p00 = __expf(sacc[nf][0] - mn0);
            const float p01 = __expf(sacc[nf][1] - mn0);
            const float p10 = __expf(sacc[nf][2] - mn1);
            const float p11 = __expf(sacc[nf][3] - mn1);
            ps0 += p00 + p01;
            ps1 += p10 + p11;
            ph[nf][0] = h2_as_u32(__floats2half2_rn(p00, p01));
            ph[nf][1] = h2_as_u32(__floats2half2_rn(p10, p11));
        }
        ps0 += __shfl_xor_sync(0xffffffffu, ps0, 1);
        ps0 += __shfl_xor_sync(0xffffffffu, ps0, 2);
        ps1 += __shfl_xor_sync(0xffffffffu, ps1, 1);
        ps1 += __shfl_xor_sync(0xffffffffu, ps1, 2);
        const float rs0 = __expf(m0 - mn0), rs1 = __expf(m1 - mn1);
        l0 = l0 * rs0 + ps0;  m0 = mn0;
        l1 = l1 * rs1 + ps1;  m1 = mn1;
#pragma unroll
        for (int nf = 0; nf < 8; nf++) {
            oacc[nf][0] *= rs0; oacc[nf][1] *= rs0;
            oacc[nf][2] *= rs1; oacc[nf][3] *= rs1;
        }

        // O += P @ V   (A fragments = re-packed S accumulators)
#pragma unroll
        for (int kb = 0; kb < 4; kb++) {
            const unsigned af[4] = { ph[2*kb][0], ph[2*kb][1], ph[2*kb+1][0], ph[2*kb+1][1] };
#pragma unroll
            for (int nd = 0; nd < 8; nd++) {
                unsigned bf[2];
                bf[0] = *(const unsigned*)&Vs[nd * 8 + g][kb * 16 + t2];
                bf[1] = *(const unsigned*)&Vs[nd * 8 + g][kb * 16 + t2 + 8];
                mma16816(oacc[nd], af, bf);
            }
        }
    }

    // epilogue: normalize, write [B,S,H*Dh] fp16
    const float i0 = 1.f / l0, i1 = 1.f / l1;
    const int row = warp * 16 + g;
    const int s0 = qt * 128 + row;
#pragma unroll
    for (int nf = 0; nf < 8; nf++) {
        const int d = h * HD + nf * 8 + t2;
        *(__half2*)&O[((size_t)(b * SEQ) + s0) * EMBD + d] =
            __floats2half2_rn(oacc[nf][0] * i0, oacc[nf][1] * i0);
        *(__half2*)&O[((size_t)(b * SEQ) + s0 + 8) * EMBD + d] =
            __floats2half2_rn(oacc[nf][2] * i1, oacc[nf][3] * i1);
    }
}

// ---------------- launch ----------------
extern "C" void kernel_launch(void* const* d_in, const int* in_sizes, int n_in,
                              void* d_out, int out_size)
{
    const float* x  = (const float*)d_in[0];
    const float* Wq = (const float*)d_in[1];
    const float* bq = (const float*)d_in[2];
    const float* Wk = (const float*)d_in[3];
    const float* bk = (const float*)d_in[4];
    const float* Wv = (const float*)d_in[5];
    const float* bv = (const float*)d_in[6];
    const float* Wo = (const float*)d_in[7];
    const float* bo = (const float*)d_in[8];
    float* out = (float*)d_out;

    __half *xh, *wqt, *wkvt, *wot, *q, *k, *vt, *ao;
    float *bkv;
    cudaGetSymbolAddress((void**)&xh,   g_xh);
    cudaGetSymbolAddress((void**)&wqt,  g_wqt);
    cudaGetSymbolAddress((void**)&wkvt, g_wkvt);
    cudaGetSymbolAddress((void**)&wot,  g_wot);
    cudaGetSymbolAddress((void**)&bkv,  g_bkv);
    cudaGetSymbolAddress((void**)&q,    g_q);
    cudaGetSymbolAddress((void**)&k,    g_k);
    cudaGetSymbolAddress((void**)&vt,   g_vt);
    cudaGetSymbolAddress((void**)&ao,   g_ao);

    // fp16 conversions / weight transposes
    f2h_kernel<<<(MROWS * EMBD / 4 + 255) / 256, 256>>>(x, xh, MROWS * EMBD / 4);
    tconv_kernel<<<dim3(EMBD / 32, EMBD / 32), dim3(32, 8)>>>(Wq, wqt, EMBD, EMBD);
    tconv_kernel<<<dim3(HD   / 32, EMBD / 32), dim3(32, 8)>>>(Wk, wkvt, EMBD, HD);
    tconv_kernel<<<dim3(HD   / 32, EMBD / 32), dim3(32, 8)>>>(Wv, wkvt + (size_t)HD * EMBD, EMBD, HD);
    tconv_kernel<<<dim3(EMBD / 32, EMBD / 32), dim3(32, 8)>>>(Wo, wot, EMBD, EMBD);
    bcat_kernel<<<1, 2 * HD>>>(bk, bv, bkv);

    // projections
    hgemm_kernel<128, 2><<<dim3(EMBD / 128, MROWS / 128), 256>>>(xh, wqt, bq, q, EMBD, EMBD);
    hgemm_kernel<128, 4><<<dim3(1,          MROWS / 128), 256>>>(xh, wkvt, bkv, k, EMBD, 2 * HD);

    // flash attention
    attn_kernel<<<dim3(SEQ / 128, BATCH * HEADS), 256>>>(q, k, vt, ao);

    // output projection -> fp32 d_out
    hgemm_kernel<128, 0><<<dim3(EMBD / 128, MROWS / 128), 256>>>(ao, wot, bo, out, EMBD, EMBD);
}